// round 15
// baseline (speedup 1.0000x reference)
#include <cuda_runtime.h>
#include <math.h>
#include <stdint.h>

// Problem dims
#define BB 2
#define CC 384
#define HH 360
#define WW 720
#define LL 180
#define MM 181
#define NF 362
#define NRr 276480               // BB*CC*HH
#define BCL 138240               // BB*CC*LL
#define NTOT 199065600

#define KF 192                   // padded fold length (181 -> 192)
#define NBF 96                   // padded mode dim per parity (91/90 -> 96)
#define KI 96                    // padded K per parity, inverse

typedef unsigned long long u64;

// ---------------- packed f32x2 helpers --------------------------------------
static __device__ __forceinline__ u64 dup2(float v) {
    u64 r;
    asm("mov.b64 %0, {%1, %1};" : "=l"(r) : "f"(v));
    return r;
}
static __device__ __forceinline__ void fma2(u64& d, u64 a, u64 b) {
    asm("fma.rn.f32x2 %0, %1, %2, %0;" : "+l"(d) : "l"(a), "l"(b));
}
static __device__ __forceinline__ float2 unpk(u64 v) {
    float2 f;
    asm("mov.b64 {%0, %1}, %2;" : "=f"(f.x), "=f"(f.y) : "l"(v));
    return f;
}

// ---------------- device globals (allocation-free; zero-init at load) ------
__device__ float g_fold4[4][(size_t)NRr * KF];   // EE, EO, OE, OO [row][k]
__device__ float g_Bf4[4][KF * NBF];             // fwd bases [z][k][n]
__device__ float g_Bi4[4][KI * 192];             // inv bases [z][k][j]
__device__ float g_xm[(size_t)384 * NRr];        // [plane][row], plane=4n+z=2m+ri
__device__ float g_cf[(size_t)NF * BCL];         // [2m+ri][bc*180+l]
__device__ float g_xm2[(size_t)384 * NRr];       // [plane][row]
__device__ float g_pctT[(size_t)MM * HH * LL];   // [m][h][l]
__device__ float g_ipctT[(size_t)MM * LL * HH];  // [m][l][h]

// ---------------- basis builders -------------------------------------------
__global__ void kb_f3() {
    int idx = blockIdx.x * 256 + threadIdx.x;
    if (idx >= 4 * KF * NBF) return;
    int z = idx / (KF * NBF);
    int r = (idx / NBF) % KF;
    int n = idx % NBF;
    float v = 0.f;
    double s, c;
    if (z == 0) {
        if (r <= 180 && n <= 90) { sincospi((double)(2 * n) * r / 360.0, &s, &c); v = (float)c; }
    } else if (z == 1) {
        if (r <= 179 && n <= 90) { sincospi((double)(2 * n) * (r + 1) / 360.0, &s, &c); v = (float)(-s); }
    } else if (z == 2) {
        if (r <= 180 && n <= 89) { sincospi((double)(2 * n + 1) * r / 360.0, &s, &c); v = (float)c; }
    } else {
        if (r <= 179 && n <= 89) { sincospi((double)(2 * n + 1) * (r + 1) / 360.0, &s, &c); v = (float)(-s); }
    }
    g_Bf4[0][idx] = v;
}

__global__ void kb_i3() {
    int idx = blockIdx.x * 256 + threadIdx.x;
    if (idx >= 4 * KI * 192) return;
    int z = idx / (KI * 192);
    int k = (idx / 192) % KI;
    int j = idx % 192;
    float v = 0.f;
    double s, c;
    if (j <= 180) {
        if (z < 2) {
            if (k <= 90) {
                int m = 2 * k;
                double sc = (m == 0 ? 1.0 : 2.0) / 720.0;
                sincospi((double)m * j / 360.0, &s, &c);
                v = (float)(sc * (z == 0 ? c : s));
            }
        } else {
            if (k <= 89) {
                int m = 2 * k + 1;
                sincospi((double)m * j / 360.0, &s, &c);
                v = (float)((2.0 / 720.0) * (z == 2 ? c : s));
            }
        }
    }
    g_Bi4[0][idx] = v;
}

// pctT[m][h][l] = pct[h][l][m]
__global__ void kT_pct(const float* __restrict__ pct) {
    size_t idx = (size_t)blockIdx.x * 256 + threadIdx.x;
    if (idx >= (size_t)MM * HH * LL) return;
    int l = (int)(idx % LL);
    size_t t = idx / LL;
    int h = (int)(t % HH);
    int m = (int)(t / HH);
    g_pctT[idx] = pct[((size_t)h * LL + l) * MM + m];
}
// ipctT[m][l][h] = ipct[h][l][m]
__global__ void kT_ipct(const float* __restrict__ ipct) {
    size_t idx = (size_t)blockIdx.x * 256 + threadIdx.x;
    if (idx >= (size_t)MM * LL * HH) return;
    int h = (int)(idx % HH);
    size_t t = idx / HH;
    int l = (int)(t % LL);
    int m = (int)(t / LL);
    g_ipctT[idx] = ipct[((size_t)h * LL + l) * MM + m];
}

// ---------------- double fold + fused residual copy -------------------------
// Every x element is read exactly once here; emit residual (out+NTOT) for free.
__global__ void k_fold4(const float* __restrict__ x, float* __restrict__ fold,
                        float* __restrict__ res, int doRes) {
    unsigned idx = blockIdx.x * 256u + threadIdx.x;
    if (idx >= (unsigned)NRr * 181u) return;
    int row = idx / 181;
    int w = idx - row * 181;
    const float* xr = x + (size_t)row * WW;
    float* EE = fold + (size_t)row * KF;
    float* EO = EE + (size_t)NRr * KF;
    float* OE = EO + (size_t)NRr * KF;
    float* OO = OE + (size_t)NRr * KF;
    float* rr = res + (size_t)row * WW;
    if (w == 0) {
        float a = xr[0], b = xr[360];
        EE[0] = a + b;
        EO[0] = a - b;
        if (doRes) { rr[0] = a; rr[360] = b; }
    } else if (w == 180) {
        float a = xr[180], b = xr[540];
        EE[180] = a + b;
        EO[180] = 0.f;
        OE[179] = 0.f;
        OO[179] = a - b;
        if (doRes) { rr[180] = a; rr[540] = b; }
    } else {
        float x1 = xr[w], x2 = xr[WW - w], x3 = xr[360 - w], x4 = xr[360 + w];
        EE[w] = x1 + x2 + x3 + x4;
        EO[w] = x1 + x2 - x3 - x4;
        OE[w - 1] = x1 - x2 - x3 + x4;
        OO[w - 1] = x1 - x2 + x3 - x4;
        if (doRes) { rr[w] = x1; rr[WW - w] = x2; rr[360 - w] = x3; rr[360 + w] = x4; }
    }
}

// ---------------- forward GEMM: 128 rows x 96 modes, f32x2 (unchanged) ------
__global__ __launch_bounds__(256) void g1f96(const float* __restrict__ fold,
                                             const float* __restrict__ Bf,
                                             float* __restrict__ xm) {
    __shared__ float As[16][132];
    __shared__ float Bs[16][96];
    int z = blockIdx.y;
    int Aidx = ((z & 1) << 1) | ((z >> 1) & 1);   // 0->EE,1->OE,2->EO,3->OO
    const float* A = fold + (size_t)Aidx * NRr * KF;
    const float* Bb = Bf + (size_t)z * (KF * NBF);
    int row0 = blockIdx.x * 128;
    int tid = threadIdx.x;
    int tx = tid & 31;   // row micro (x4)
    int ty = tid >> 5;   // col micro (x12 = 6 pairs)
    u64 acc[6][4];
#pragma unroll
    for (int j = 0; j < 6; j++)
#pragma unroll
        for (int i = 0; i < 4; i++) acc[j][i] = 0ull;

    int lr = tid >> 1, lkq = (tid & 1) * 8;
    const float* arow = A + (size_t)(row0 + lr) * KF + lkq;

    for (int k0 = 0; k0 < KF; k0 += 16) {
        {
            float4 v0 = *(const float4*)(arow + k0);
            float4 v1 = *(const float4*)(arow + k0 + 4);
            As[lkq + 0][lr] = v0.x; As[lkq + 1][lr] = v0.y;
            As[lkq + 2][lr] = v0.z; As[lkq + 3][lr] = v0.w;
            As[lkq + 4][lr] = v1.x; As[lkq + 5][lr] = v1.y;
            As[lkq + 6][lr] = v1.z; As[lkq + 7][lr] = v1.w;
        }
#pragma unroll
        for (int p = 0; p < 2; p++) {
            int i = tid + p * 256;
            if (i < 384) {
                int k = i / 24, c4 = (i % 24) * 4;
                *(float4*)&Bs[k][c4] = *(const float4*)(Bb + (size_t)(k0 + k) * NBF + c4);
            }
        }
        __syncthreads();
#pragma unroll
        for (int kk = 0; kk < 16; kk++) {
            float4 a4 = *(const float4*)&As[kk][tx * 4];
            const ulonglong2* bp = (const ulonglong2*)&Bs[kk][ty * 12];
            ulonglong2 b01 = bp[0];
            u64 b45 = ((const u64*)bp)[4];
            ulonglong2 b23 = bp[1];
            u64 ad[4] = {dup2(a4.x), dup2(a4.y), dup2(a4.z), dup2(a4.w)};
            u64 bv[6] = {b01.x, b01.y, b23.x, b23.y, b45, ((const u64*)bp)[5]};
#pragma unroll
            for (int j = 0; j < 6; j++)
#pragma unroll
                for (int i = 0; i < 4; i++) fma2(acc[j][i], ad[i], bv[j]);
        }
        __syncthreads();
    }
#pragma unroll
    for (int j = 0; j < 6; j++) {
        float2 u0 = unpk(acc[j][0]), u1 = unpk(acc[j][1]);
        float2 u2 = unpk(acc[j][2]), u3 = unpk(acc[j][3]);
        int n = ty * 12 + 2 * j;
        float4 e = make_float4(u0.x, u1.x, u2.x, u3.x);
        float4 o = make_float4(u0.y, u1.y, u2.y, u3.y);
        *(float4*)(xm + (size_t)(4 * n + z) * NRr + row0 + tx * 4) = e;
        *(float4*)(xm + (size_t)(4 * (n + 1) + z) * NRr + row0 + tx * 4) = o;
    }
}

// ---------------- K2 wide: 64 bc x 192 l, xm read once ----------------------
__global__ __launch_bounds__(256) void k2w(const float* __restrict__ weight) {
    int m = blockIdx.y;
    int bc0 = blockIdx.x * 64;
    __shared__ float Ar[8][64], Ai[8][64], Ps[8][200];
    int tid = threadIdx.x;
    int tx = tid & 15;   // l micro (x12 = 6 pairs... packed along bc)
    int ty = tid >> 4;   // bc micro (x4 = 2 pairs)
    u64 accR[2][12], accI[2][12];
#pragma unroll
    for (int i = 0; i < 2; i++)
#pragma unroll
        for (int j = 0; j < 12; j++) { accR[i][j] = 0ull; accI[i][j] = 0ull; }

    const float* xr = g_xm + (size_t)(2 * m) * NRr;
    const float* xi = xr + NRr;

    for (int h0 = 0; h0 < HH; h0 += 8) {
        {
            int r = tid >> 2;
            int k2v = (tid & 3) * 2;
            size_t base = (size_t)(bc0 + r) * HH + h0 + k2v;
            float2 vr = *(const float2*)(xr + base);
            Ar[k2v][r] = vr.x; Ar[k2v + 1][r] = vr.y;
            float2 vi = *(const float2*)(xi + base);
            Ai[k2v][r] = vi.x; Ai[k2v + 1][r] = vi.y;
        }
#pragma unroll
        for (int p = 0; p < 2; p++) {
            int idx4 = tid + p * 256;
            if (idx4 < 384) {
                int k = idx4 / 48;
                int jq = (idx4 % 48) * 4;
                const float* src = g_pctT + ((size_t)m * HH + h0 + k) * LL + jq;
                if (jq < 180) {
                    *(float4*)&Ps[k][jq] = *(const float4*)src;
                } else {
                    *(float4*)&Ps[k][jq] = make_float4(0.f, 0.f, 0.f, 0.f);
                }
            }
        }
        __syncthreads();
#pragma unroll
        for (int kk = 0; kk < 8; kk++) {
            ulonglong2 ar2 = *(const ulonglong2*)&Ar[kk][ty * 4];
            ulonglong2 ai2 = *(const ulonglong2*)&Ai[kk][ty * 4];
            const float4* pp = (const float4*)&Ps[kk][tx * 12];
            float4 p0 = pp[0], p1 = pp[1], p2 = pp[2];
            u64 pb[12] = {dup2(p0.x), dup2(p0.y), dup2(p0.z), dup2(p0.w),
                          dup2(p1.x), dup2(p1.y), dup2(p1.z), dup2(p1.w),
                          dup2(p2.x), dup2(p2.y), dup2(p2.z), dup2(p2.w)};
            u64 arv[2] = {ar2.x, ar2.y};
            u64 aiv[2] = {ai2.x, ai2.y};
#pragma unroll
            for (int i = 0; i < 2; i++)
#pragma unroll
                for (int j = 0; j < 12; j++) {
                    fma2(accR[i][j], arv[i], pb[j]);
                    fma2(accI[i][j], aiv[i], pb[j]);
                }
        }
        __syncthreads();
    }
    float* cr = g_cf + (size_t)(2 * m) * BCL;
    float* ci = cr + BCL;
#pragma unroll
    for (int i2 = 0; i2 < 2; i2++) {
#pragma unroll
        for (int j = 0; j < 12; j++) {
            int l = tx * 12 + j;
            if (l >= LL) continue;
            float2 vR = unpk(accR[i2][j]);
            float2 vI = unpk(accI[i2][j]);
#pragma unroll
            for (int lane = 0; lane < 2; lane++) {
                int bc = bc0 + ty * 4 + 2 * i2 + lane;
                int c = bc % CC;
                float aR = lane ? vR.y : vR.x;
                float aI = lane ? vI.y : vI.x;
                float2 wv = *(const float2*)(weight + (((size_t)c * LL + l) * MM + m) * 2);
                size_t o = (size_t)bc * LL + l;
                cr[o] = aR * wv.x - aI * wv.y;
                ci[o] = aR * wv.y + aI * wv.x;
            }
        }
    }
}

// ---------------- K3 wide: 64 bc x 192 h, cf reads 6x -> 2x -----------------
__global__ __launch_bounds__(256) void k3w() {
    int m = blockIdx.z;
    int bc0 = blockIdx.x * 64;
    int h0 = blockIdx.y * 192;
    __shared__ float Ar[8][64], Ai[8][64], Qs[8][200];
    int tid = threadIdx.x;
    int tx = tid & 15;   // h micro (x12)
    int ty = tid >> 4;   // bc micro (x4 = 2 pairs)
    u64 accR[2][12], accI[2][12];
#pragma unroll
    for (int i = 0; i < 2; i++)
#pragma unroll
        for (int j = 0; j < 12; j++) { accR[i][j] = 0ull; accI[i][j] = 0ull; }

    const float* cr = g_cf + (size_t)(2 * m) * BCL;
    const float* ci = cr + BCL;

    for (int l0 = 0; l0 < LL; l0 += 8) {
        {
            int r = tid >> 2;
            int k2v = (tid & 3) * 2;
            int l = l0 + k2v;
            size_t base = (size_t)(bc0 + r) * LL + l;
            Ar[k2v][r]     = (l < LL)     ? cr[base]     : 0.f;
            Ar[k2v + 1][r] = (l + 1 < LL) ? cr[base + 1] : 0.f;
            Ai[k2v][r]     = (l < LL)     ? ci[base]     : 0.f;
            Ai[k2v + 1][r] = (l + 1 < LL) ? ci[base + 1] : 0.f;
        }
#pragma unroll
        for (int p = 0; p < 2; p++) {
            int idx4 = tid + p * 256;
            if (idx4 < 384) {
                int k = idx4 / 48;
                int jq = (idx4 % 48) * 4;
                int l = l0 + k;
                if (l < LL && h0 + jq < HH) {
                    *(float4*)&Qs[k][jq] =
                        *(const float4*)(g_ipctT + ((size_t)m * LL + l) * HH + h0 + jq);
                } else {
                    *(float4*)&Qs[k][jq] = make_float4(0.f, 0.f, 0.f, 0.f);
                }
            }
        }
        __syncthreads();
#pragma unroll
        for (int kk = 0; kk < 8; kk++) {
            ulonglong2 ar2 = *(const ulonglong2*)&Ar[kk][ty * 4];
            ulonglong2 ai2 = *(const ulonglong2*)&Ai[kk][ty * 4];
            const float4* qp = (const float4*)&Qs[kk][tx * 12];
            float4 q0 = qp[0], q1 = qp[1], q2 = qp[2];
            u64 qb[12] = {dup2(q0.x), dup2(q0.y), dup2(q0.z), dup2(q0.w),
                          dup2(q1.x), dup2(q1.y), dup2(q1.z), dup2(q1.w),
                          dup2(q2.x), dup2(q2.y), dup2(q2.z), dup2(q2.w)};
            u64 arv[2] = {ar2.x, ar2.y};
            u64 aiv[2] = {ai2.x, ai2.y};
#pragma unroll
            for (int i = 0; i < 2; i++)
#pragma unroll
                for (int j = 0; j < 12; j++) {
                    fma2(accR[i][j], arv[i], qb[j]);
                    fma2(accI[i][j], aiv[i], qb[j]);
                }
        }
        __syncthreads();
    }
    float* orp = g_xm2 + (size_t)(2 * m) * NRr;
    float* oip = orp + NRr;
#pragma unroll
    for (int i2 = 0; i2 < 2; i2++) {
#pragma unroll
        for (int j = 0; j < 12; j++) {
            int h = h0 + tx * 12 + j;
            if (h >= HH) continue;
            float2 vR = unpk(accR[i2][j]);
            float2 vI = unpk(accI[i2][j]);
#pragma unroll
            for (int lane = 0; lane < 2; lane++) {
                int bc = bc0 + ty * 4 + 2 * i2 + lane;
                size_t o = (size_t)bc * HH + h;
                orp[o] = lane ? vR.y : vR.x;
                oip[o] = lane ? vI.y : vI.x;
            }
        }
    }
}

// ---------------- inverse GEMM + fused combine: 32 rows x 192 j -------------
// xm2 read exactly once. Write order per (row,jj) matches the passing R10 path.
__global__ __launch_bounds__(256) void g4cw(const float* __restrict__ xm2,
                                            const float* __restrict__ Bi,
                                            float* __restrict__ out) {
    __shared__ float As[4][8][36];
    __shared__ float Bs[4][8][200];
    int row0 = blockIdx.x * 32;
    int tid = threadIdx.x;
    int tx = tid & 15;   // j micro (x12 = 6 pairs)
    int ty = tid >> 4;   // row micro (x2)
    u64 acc[4][2][6];    // [z][row][j-pair]
#pragma unroll
    for (int z = 0; z < 4; z++)
#pragma unroll
        for (int i = 0; i < 2; i++)
#pragma unroll
            for (int j = 0; j < 6; j++) acc[z][i][j] = 0ull;

    for (int k0 = 0; k0 < KI; k0 += 8) {
        {   // As: 4z x 8k x 32 rows = 256 float4, one per thread
            int z = tid >> 6, rem = tid & 63;
            int k = rem >> 3, rq = (rem & 7) * 4;
            *(float4*)&As[z][k][rq] =
                *(const float4*)(xm2 + (size_t)(4 * (k0 + k) + z) * NRr + row0 + rq);
        }
#pragma unroll
        for (int p = 0; p < 6; p++) {   // Bs: 4z x 8k x 192j = 1536 float4
            int idx4 = tid + p * 256;
            int z = idx4 / 384, rem = idx4 % 384;
            int k = rem / 48, jq = (rem % 48) * 4;
            *(float4*)&Bs[z][k][jq] =
                *(const float4*)(Bi + (size_t)z * (KI * 192) + (size_t)(k0 + k) * 192 + jq);
        }
        __syncthreads();
#pragma unroll
        for (int kk = 0; kk < 8; kk++) {
#pragma unroll
            for (int z = 0; z < 4; z++) {
                float2 a2 = *(const float2*)&As[z][kk][ty * 2];
                u64 ad[2] = {dup2(a2.x), dup2(a2.y)};
                const ulonglong2* bp = (const ulonglong2*)&Bs[z][kk][tx * 12];
                ulonglong2 b01 = bp[0];
                ulonglong2 b23 = bp[1];
                u64 bv[6] = {b01.x, b01.y, b23.x, b23.y,
                             ((const u64*)bp)[4], ((const u64*)bp)[5]};
#pragma unroll
                for (int i = 0; i < 2; i++)
#pragma unroll
                    for (int j = 0; j < 6; j++) fma2(acc[z][i][j], ad[i], bv[j]);
            }
        }
        __syncthreads();
    }
    // fused combine epilogue (exact write order of the passing version)
#pragma unroll
    for (int i = 0; i < 2; i++) {
        int row = row0 + ty * 2 + i;
        float* o = out + (size_t)row * WW;
#pragma unroll
        for (int jp = 0; jp < 6; jp++) {
            float2 v0 = unpk(acc[0][i][jp]);
            float2 v1 = unpk(acc[1][i][jp]);
            float2 v2 = unpk(acc[2][i][jp]);
            float2 v3 = unpk(acc[3][i][jp]);
#pragma unroll
            for (int lane = 0; lane < 2; lane++) {
                int jj = tx * 12 + 2 * jp + lane;
                if (jj > 180) continue;
                float q0 = lane ? v0.y : v0.x;
                float q1 = lane ? v1.y : v1.x;
                float q2 = lane ? v2.y : v2.x;
                float q3 = lane ? v3.y : v3.x;
                float a = q0 + q2, b = q1 + q3, c = q0 - q2, d = q1 - q3;
                o[jj] = a - b;
                o[360 - jj] = c + d;
                if (jj >= 1) {
                    o[WW - jj] = a + b;
                    o[360 + jj] = c - d;
                }
            }
        }
    }
}

// ---------------------------------------------------------------------------
extern "C" void kernel_launch(void* const* d_in, const int* in_sizes, int n_in,
                              void* d_out, int out_size) {
    const float* x      = (const float*)d_in[0];
    const float* weight = (const float*)d_in[1];
    const float* pct    = (const float*)d_in[2];
    const float* ipct   = (const float*)d_in[3];
    float* out = (float*)d_out;

    // Resolve REAL device addresses (host-side &symbol is the shadow).
    float *p_fold, *p_Bf, *p_Bi, *p_xm, *p_xm2;
    cudaGetSymbolAddress((void**)&p_fold, g_fold4);
    cudaGetSymbolAddress((void**)&p_Bf,   g_Bf4);
    cudaGetSymbolAddress((void**)&p_Bi,   g_Bi4);
    cudaGetSymbolAddress((void**)&p_xm,   g_xm);
    cudaGetSymbolAddress((void**)&p_xm2,  g_xm2);

    int doRes = ((long long)out_size >= 2LL * NTOT) ? 1 : 0;

    kb_f3<<<(4 * KF * NBF + 255) / 256, 256>>>();
    kb_i3<<<(4 * KI * 192 + 255) / 256, 256>>>();
    {
        size_t n = (size_t)MM * HH * LL;
        kT_pct<<<(unsigned)((n + 255) / 256), 256>>>(pct);
        kT_ipct<<<(unsigned)((n + 255) / 256), 256>>>(ipct);
    }
    // Fold + residual copy fused (memcpy eliminated)
    k_fold4<<<(NRr * 181 + 255) / 256, 256>>>(x, p_fold, out + NTOT, doRes);

    g1f96<<<dim3(NRr / 128, 4), 256>>>(p_fold, p_Bf, p_xm);

    k2w<<<dim3(12, MM), 256>>>(weight);
    k3w<<<dim3(12, 2, MM), 256>>>();

    g4cw<<<NRr / 32, 256>>>(p_xm2, p_Bi, out);
}

// round 16
// speedup vs baseline: 2.2089x; 2.2089x over previous
#include <cuda_runtime.h>
#include <math.h>
#include <stdint.h>

// Problem dims
#define BB 2
#define CC 384
#define HH 360
#define WW 720
#define LL 180
#define MM 181
#define NF 362
#define NRr 276480               // BB*CC*HH
#define BCL 138240               // BB*CC*LL
#define NTOT 199065600

#define KF 192                   // padded fold length (181 -> 192)
#define NBF 96                   // padded mode dim per parity (91/90 -> 96)
#define KI 96                    // padded K per parity, inverse

typedef unsigned long long u64;

// ---------------- packed f32x2 helpers --------------------------------------
static __device__ __forceinline__ u64 dup2(float v) {
    u64 r;
    asm("mov.b64 %0, {%1, %1};" : "=l"(r) : "f"(v));
    return r;
}
static __device__ __forceinline__ void fma2(u64& d, u64 a, u64 b) {
    asm("fma.rn.f32x2 %0, %1, %2, %0;" : "+l"(d) : "l"(a), "l"(b));
}
static __device__ __forceinline__ float2 unpk(u64 v) {
    float2 f;
    asm("mov.b64 {%0, %1}, %2;" : "=f"(f.x), "=f"(f.y) : "l"(v));
    return f;
}

// ---------------- device globals (allocation-free; zero-init at load) ------
__device__ float g_fold4[4][(size_t)NRr * KF];   // EE, EO, OE, OO [row][k]
__device__ float g_Bf4[4][KF * NBF];             // fwd bases [z][k][n]
__device__ float g_Bi4[4][KI * 192];             // inv bases [z][k][j]
__device__ float g_xm[(size_t)384 * NRr];        // [plane][row], plane=4n+z=2m+ri
__device__ float g_cf[(size_t)NF * BCL];         // [2m+ri][bc*180+l]
__device__ float g_xm2[(size_t)384 * NRr];       // [plane][row]
__device__ float g_pctT[(size_t)MM * HH * LL];   // [m][h][l]
__device__ float g_ipctT[(size_t)MM * LL * HH];  // [m][l][h]

// ---------------- basis builders -------------------------------------------
__global__ void kb_f3() {
    int idx = blockIdx.x * 256 + threadIdx.x;
    if (idx >= 4 * KF * NBF) return;
    int z = idx / (KF * NBF);
    int r = (idx / NBF) % KF;
    int n = idx % NBF;
    float v = 0.f;
    double s, c;
    if (z == 0) {
        if (r <= 180 && n <= 90) { sincospi((double)(2 * n) * r / 360.0, &s, &c); v = (float)c; }
    } else if (z == 1) {
        if (r <= 179 && n <= 90) { sincospi((double)(2 * n) * (r + 1) / 360.0, &s, &c); v = (float)(-s); }
    } else if (z == 2) {
        if (r <= 180 && n <= 89) { sincospi((double)(2 * n + 1) * r / 360.0, &s, &c); v = (float)c; }
    } else {
        if (r <= 179 && n <= 89) { sincospi((double)(2 * n + 1) * (r + 1) / 360.0, &s, &c); v = (float)(-s); }
    }
    g_Bf4[0][idx] = v;
}

__global__ void kb_i3() {
    int idx = blockIdx.x * 256 + threadIdx.x;
    if (idx >= 4 * KI * 192) return;
    int z = idx / (KI * 192);
    int k = (idx / 192) % KI;
    int j = idx % 192;
    float v = 0.f;
    double s, c;
    if (j <= 180) {
        if (z < 2) {
            if (k <= 90) {
                int m = 2 * k;
                double sc = (m == 0 ? 1.0 : 2.0) / 720.0;
                sincospi((double)m * j / 360.0, &s, &c);
                v = (float)(sc * (z == 0 ? c : s));
            }
        } else {
            if (k <= 89) {
                int m = 2 * k + 1;
                sincospi((double)m * j / 360.0, &s, &c);
                v = (float)((2.0 / 720.0) * (z == 2 ? c : s));
            }
        }
    }
    g_Bi4[0][idx] = v;
}

// pctT[m][h][l] = pct[h][l][m]
__global__ void kT_pct(const float* __restrict__ pct) {
    size_t idx = (size_t)blockIdx.x * 256 + threadIdx.x;
    if (idx >= (size_t)MM * HH * LL) return;
    int l = (int)(idx % LL);
    size_t t = idx / LL;
    int h = (int)(t % HH);
    int m = (int)(t / HH);
    g_pctT[idx] = pct[((size_t)h * LL + l) * MM + m];
}
// ipctT[m][l][h] = ipct[h][l][m]
__global__ void kT_ipct(const float* __restrict__ ipct) {
    size_t idx = (size_t)blockIdx.x * 256 + threadIdx.x;
    if (idx >= (size_t)MM * LL * HH) return;
    int h = (int)(idx % HH);
    size_t t = idx / HH;
    int l = (int)(t % LL);
    int m = (int)(t / LL);
    g_ipctT[idx] = ipct[((size_t)h * LL + l) * MM + m];
}

// ---------------- double fold + fused residual copy -------------------------
// Every x element is read exactly once here; emit the residual in the same
// pass (removes the 1.6 GB cudaMemcpyAsync node: saves its 800 MB read).
__global__ void k_fold4(const float* __restrict__ x, float* __restrict__ fold,
                        float* __restrict__ res, int doRes) {
    unsigned idx = blockIdx.x * 256u + threadIdx.x;
    if (idx >= (unsigned)NRr * 181u) return;
    int row = idx / 181;
    int w = idx - row * 181;
    const float* xr = x + (size_t)row * WW;
    float* EE = fold + (size_t)row * KF;
    float* EO = EE + (size_t)NRr * KF;
    float* OE = EO + (size_t)NRr * KF;
    float* OO = OE + (size_t)NRr * KF;
    float* rr = res + (size_t)row * WW;
    if (w == 0) {
        float a = xr[0], b = xr[360];
        EE[0] = a + b;
        EO[0] = a - b;
        if (doRes) { rr[0] = a; rr[360] = b; }
    } else if (w == 180) {
        float a = xr[180], b = xr[540];
        EE[180] = a + b;
        EO[180] = 0.f;
        OE[179] = 0.f;
        OO[179] = a - b;
        if (doRes) { rr[180] = a; rr[540] = b; }
    } else {
        float x1 = xr[w], x2 = xr[WW - w], x3 = xr[360 - w], x4 = xr[360 + w];
        EE[w] = x1 + x2 + x3 + x4;
        EO[w] = x1 + x2 - x3 - x4;
        OE[w - 1] = x1 - x2 - x3 + x4;
        OO[w - 1] = x1 - x2 + x3 - x4;
        if (doRes) { rr[w] = x1; rr[WW - w] = x2; rr[360 - w] = x3; rr[360 + w] = x4; }
    }
}

// ---------------- forward GEMM: 128 rows x 96 modes, f32x2 (R14 verbatim) ---
__global__ __launch_bounds__(256) void g1f96(const float* __restrict__ fold,
                                             const float* __restrict__ Bf,
                                             float* __restrict__ xm) {
    __shared__ float As[16][132];
    __shared__ float Bs[16][96];
    int z = blockIdx.y;
    int Aidx = ((z & 1) << 1) | ((z >> 1) & 1);   // 0->EE,1->OE,2->EO,3->OO
    const float* A = fold + (size_t)Aidx * NRr * KF;
    const float* Bb = Bf + (size_t)z * (KF * NBF);
    int row0 = blockIdx.x * 128;
    int tid = threadIdx.x;
    int tx = tid & 31;   // row micro (x4)
    int ty = tid >> 5;   // col micro (x12 = 6 pairs)
    u64 acc[6][4];
#pragma unroll
    for (int j = 0; j < 6; j++)
#pragma unroll
        for (int i = 0; i < 4; i++) acc[j][i] = 0ull;

    int lr = tid >> 1, lkq = (tid & 1) * 8;
    const float* arow = A + (size_t)(row0 + lr) * KF + lkq;

    for (int k0 = 0; k0 < KF; k0 += 16) {
        {
            float4 v0 = *(const float4*)(arow + k0);
            float4 v1 = *(const float4*)(arow + k0 + 4);
            As[lkq + 0][lr] = v0.x; As[lkq + 1][lr] = v0.y;
            As[lkq + 2][lr] = v0.z; As[lkq + 3][lr] = v0.w;
            As[lkq + 4][lr] = v1.x; As[lkq + 5][lr] = v1.y;
            As[lkq + 6][lr] = v1.z; As[lkq + 7][lr] = v1.w;
        }
#pragma unroll
        for (int p = 0; p < 2; p++) {
            int i = tid + p * 256;
            if (i < 384) {
                int k = i / 24, c4 = (i % 24) * 4;
                *(float4*)&Bs[k][c4] = *(const float4*)(Bb + (size_t)(k0 + k) * NBF + c4);
            }
        }
        __syncthreads();
#pragma unroll
        for (int kk = 0; kk < 16; kk++) {
            float4 a4 = *(const float4*)&As[kk][tx * 4];
            const ulonglong2* bp = (const ulonglong2*)&Bs[kk][ty * 12];
            ulonglong2 b01 = bp[0];
            u64 b45 = ((const u64*)bp)[4];
            ulonglong2 b23 = bp[1];
            u64 ad[4] = {dup2(a4.x), dup2(a4.y), dup2(a4.z), dup2(a4.w)};
            u64 bv[6] = {b01.x, b01.y, b23.x, b23.y, b45, ((const u64*)bp)[5]};
#pragma unroll
            for (int j = 0; j < 6; j++)
#pragma unroll
                for (int i = 0; i < 4; i++) fma2(acc[j][i], ad[i], bv[j]);
        }
        __syncthreads();
    }
#pragma unroll
    for (int j = 0; j < 6; j++) {
        float2 u0 = unpk(acc[j][0]), u1 = unpk(acc[j][1]);
        float2 u2 = unpk(acc[j][2]), u3 = unpk(acc[j][3]);
        int n = ty * 12 + 2 * j;
        float4 e = make_float4(u0.x, u1.x, u2.x, u3.x);
        float4 o = make_float4(u0.y, u1.y, u2.y, u3.y);
        *(float4*)(xm + (size_t)(4 * n + z) * NRr + row0 + tx * 4) = e;
        *(float4*)(xm + (size_t)(4 * (n + 1) + z) * NRr + row0 + tx * 4) = o;
    }
}

// ---------------- K2 (f32x2, packed along bc — R14 verbatim) ----------------
__global__ __launch_bounds__(256) void k2_pct(const float* __restrict__ weight) {
    int m = blockIdx.z;
    int bc0 = blockIdx.x * 64;
    int l0 = blockIdx.y * 64;
    __shared__ float Ar[8][64], Ai[8][64], Ps[8][64];
    int tid = threadIdx.x;
    int tx = tid & 15;
    int ty = tid >> 4;
    u64 accR[2][4], accI[2][4];   // [bc-pair][l]
#pragma unroll
    for (int i = 0; i < 2; i++)
#pragma unroll
        for (int j = 0; j < 4; j++) { accR[i][j] = 0ull; accI[i][j] = 0ull; }

    const float* xr = g_xm + (size_t)(2 * m) * NRr;
    const float* xi = xr + NRr;

    for (int h0 = 0; h0 < HH; h0 += 8) {
        {
            int r = tid >> 2;
            int k2 = (tid & 3) * 2;
            size_t base = (size_t)(bc0 + r) * HH + h0 + k2;
            float2 vr = *(const float2*)(xr + base);
            Ar[k2][r] = vr.x; Ar[k2 + 1][r] = vr.y;
            float2 vi = *(const float2*)(xi + base);
            Ai[k2][r] = vi.x; Ai[k2 + 1][r] = vi.y;
        }
        {
            int k = tid >> 5;
            int c2 = (tid & 31) * 2;
            const float* Pm = g_pctT + ((size_t)m * HH + h0 + k) * LL;
#pragma unroll
            for (int j = 0; j < 2; j++) {
                int l = l0 + c2 + j;
                Ps[k][c2 + j] = (l < LL) ? Pm[l] : 0.f;
            }
        }
        __syncthreads();
#pragma unroll
        for (int k = 0; k < 8; k++) {
            ulonglong2 ar2 = *(const ulonglong2*)&Ar[k][ty * 4];
            ulonglong2 ai2 = *(const ulonglong2*)&Ai[k][ty * 4];
            float4 p4 = *(const float4*)&Ps[k][tx * 4];
            u64 pb[4] = {dup2(p4.x), dup2(p4.y), dup2(p4.z), dup2(p4.w)};
            u64 arv[2] = {ar2.x, ar2.y};
            u64 aiv[2] = {ai2.x, ai2.y};
#pragma unroll
            for (int i = 0; i < 2; i++)
#pragma unroll
                for (int j = 0; j < 4; j++) {
                    fma2(accR[i][j], arv[i], pb[j]);
                    fma2(accI[i][j], aiv[i], pb[j]);
                }
        }
        __syncthreads();
    }
    float* cr = g_cf + (size_t)(2 * m) * BCL;
    float* ci = cr + BCL;
#pragma unroll
    for (int i2 = 0; i2 < 2; i2++) {
#pragma unroll
        for (int j = 0; j < 4; j++) {
            float2 vR = unpk(accR[i2][j]);
            float2 vI = unpk(accI[i2][j]);
            int l = l0 + tx * 4 + j;
            if (l >= LL) continue;
#pragma unroll
            for (int lane = 0; lane < 2; lane++) {
                int bc = bc0 + ty * 4 + 2 * i2 + lane;
                int c = bc % CC;
                float aR = lane ? vR.y : vR.x;
                float aI = lane ? vI.y : vI.x;
                float2 wv = *(const float2*)(weight + (((size_t)c * LL + l) * MM + m) * 2);
                size_t o = (size_t)bc * LL + l;
                cr[o] = aR * wv.x - aI * wv.y;
                ci[o] = aR * wv.y + aI * wv.x;
            }
        }
    }
}

// ---------------- K3 (f32x2, packed along bc — R14 verbatim) ----------------
__global__ __launch_bounds__(256) void k3_ipct() {
    int m = blockIdx.z;
    int bc0 = blockIdx.x * 64;
    int h0 = blockIdx.y * 64;
    __shared__ float Ar[8][64], Ai[8][64], Qs[8][64];
    int tid = threadIdx.x;
    int tx = tid & 15;
    int ty = tid >> 4;
    u64 accR[2][4], accI[2][4];
#pragma unroll
    for (int i = 0; i < 2; i++)
#pragma unroll
        for (int j = 0; j < 4; j++) { accR[i][j] = 0ull; accI[i][j] = 0ull; }

    const float* cr = g_cf + (size_t)(2 * m) * BCL;
    const float* ci = cr + BCL;

    for (int l0 = 0; l0 < LL; l0 += 8) {
        {
            int r = tid >> 2;
            int k2 = (tid & 3) * 2;
            int l = l0 + k2;
            size_t base = (size_t)(bc0 + r) * LL + l;
            Ar[k2][r]     = (l < LL)     ? cr[base]     : 0.f;
            Ar[k2 + 1][r] = (l + 1 < LL) ? cr[base + 1] : 0.f;
            Ai[k2][r]     = (l < LL)     ? ci[base]     : 0.f;
            Ai[k2 + 1][r] = (l + 1 < LL) ? ci[base + 1] : 0.f;
        }
        {
            int k = tid >> 5;
            int c2 = (tid & 31) * 2;
            int l = l0 + k;
            const float* Qm = g_ipctT + ((size_t)m * LL + l) * HH;
#pragma unroll
            for (int j = 0; j < 2; j++) {
                int h = h0 + c2 + j;
                Qs[k][c2 + j] = (l < LL && h < HH) ? Qm[h] : 0.f;
            }
        }
        __syncthreads();
#pragma unroll
        for (int k = 0; k < 8; k++) {
            ulonglong2 ar2 = *(const ulonglong2*)&Ar[k][ty * 4];
            ulonglong2 ai2 = *(const ulonglong2*)&Ai[k][ty * 4];
            float4 q4 = *(const float4*)&Qs[k][tx * 4];
            u64 qb[4] = {dup2(q4.x), dup2(q4.y), dup2(q4.z), dup2(q4.w)};
            u64 arv[2] = {ar2.x, ar2.y};
            u64 aiv[2] = {ai2.x, ai2.y};
#pragma unroll
            for (int i = 0; i < 2; i++)
#pragma unroll
                for (int j = 0; j < 4; j++) {
                    fma2(accR[i][j], arv[i], qb[j]);
                    fma2(accI[i][j], aiv[i], qb[j]);
                }
        }
        __syncthreads();
    }
    float* orp = g_xm2 + (size_t)(2 * m) * NRr;
    float* oip = orp + NRr;
#pragma unroll
    for (int i2 = 0; i2 < 2; i2++) {
#pragma unroll
        for (int j = 0; j < 4; j++) {
            float2 vR = unpk(accR[i2][j]);
            float2 vI = unpk(accI[i2][j]);
            int h = h0 + tx * 4 + j;
            if (h >= HH) continue;
#pragma unroll
            for (int lane = 0; lane < 2; lane++) {
                int bc = bc0 + ty * 4 + 2 * i2 + lane;
                size_t o = (size_t)bc * HH + h;
                orp[o] = lane ? vR.y : vR.x;
                oip[o] = lane ? vI.y : vI.x;
            }
        }
    }
}

// ---------------- inverse GEMM + fused combine (f32x2 — R14 verbatim) -------
__global__ __launch_bounds__(256) void g4c(const float* __restrict__ xm2,
                                           const float* __restrict__ Bi,
                                           float* __restrict__ out) {
    __shared__ float As[4][16][68];
    __shared__ float Bs[4][16][68];
    int row0 = blockIdx.x * 64;
    int j0 = blockIdx.y * 64;
    int tid = threadIdx.x;
    int tx = tid & 15;   // j micro (x4 = 2 pairs)
    int ty = tid >> 4;   // row micro (x4)
    u64 acc[4][4][2];    // [z][row i][j-pair]
#pragma unroll
    for (int z = 0; z < 4; z++)
#pragma unroll
        for (int i = 0; i < 4; i++)
#pragma unroll
            for (int j = 0; j < 2; j++) acc[z][i][j] = 0ull;

    for (int k0 = 0; k0 < KI; k0 += 16) {
#pragma unroll
        for (int p = 0; p < 4; p++) {
            int i = tid + p * 256;
            int z = i >> 8, k = (i >> 4) & 15, c4 = (i & 15) * 4;
            *(float4*)&As[z][k][c4] =
                *(const float4*)(xm2 + (size_t)(4 * (k0 + k) + z) * NRr + row0 + c4);
            *(float4*)&Bs[z][k][c4] =
                *(const float4*)(Bi + (size_t)z * (KI * 192) + (size_t)(k0 + k) * 192 + j0 + c4);
        }
        __syncthreads();
#pragma unroll
        for (int kk = 0; kk < 16; kk++) {
#pragma unroll
            for (int z = 0; z < 4; z++) {
                float4 a4 = *(const float4*)&As[z][kk][ty * 4];
                ulonglong2 b2 = *(const ulonglong2*)&Bs[z][kk][tx * 4];
                u64 ad[4] = {dup2(a4.x), dup2(a4.y), dup2(a4.z), dup2(a4.w)};
                u64 bv[2] = {b2.x, b2.y};
#pragma unroll
                for (int i = 0; i < 4; i++)
#pragma unroll
                    for (int j = 0; j < 2; j++) fma2(acc[z][i][j], ad[i], bv[j]);
            }
        }
        __syncthreads();
    }
    // fused combine epilogue
#pragma unroll
    for (int i = 0; i < 4; i++) {
        int row = row0 + ty * 4 + i;
        float* o = out + (size_t)row * WW;
#pragma unroll
        for (int jp = 0; jp < 2; jp++) {
            float2 v0 = unpk(acc[0][i][jp]);
            float2 v1 = unpk(acc[1][i][jp]);
            float2 v2 = unpk(acc[2][i][jp]);
            float2 v3 = unpk(acc[3][i][jp]);
#pragma unroll
            for (int lane = 0; lane < 2; lane++) {
                int jj = j0 + tx * 4 + 2 * jp + lane;
                if (jj > 180) continue;
                float q0 = lane ? v0.y : v0.x;
                float q1 = lane ? v1.y : v1.x;
                float q2 = lane ? v2.y : v2.x;
                float q3 = lane ? v3.y : v3.x;
                float a = q0 + q2, b = q1 + q3, c = q0 - q2, d = q1 - q3;
                o[jj] = a - b;
                o[360 - jj] = c + d;
                if (jj >= 1) {
                    o[WW - jj] = a + b;
                    o[360 + jj] = c - d;
                }
            }
        }
    }
}

// ---------------------------------------------------------------------------
extern "C" void kernel_launch(void* const* d_in, const int* in_sizes, int n_in,
                              void* d_out, int out_size) {
    const float* x      = (const float*)d_in[0];
    const float* weight = (const float*)d_in[1];
    const float* pct    = (const float*)d_in[2];
    const float* ipct   = (const float*)d_in[3];
    float* out = (float*)d_out;

    // Resolve REAL device addresses (host-side &symbol is the shadow).
    float *p_fold, *p_Bf, *p_Bi, *p_xm, *p_xm2;
    cudaGetSymbolAddress((void**)&p_fold, g_fold4);
    cudaGetSymbolAddress((void**)&p_Bf,   g_Bf4);
    cudaGetSymbolAddress((void**)&p_Bi,   g_Bi4);
    cudaGetSymbolAddress((void**)&p_xm,   g_xm);
    cudaGetSymbolAddress((void**)&p_xm2,  g_xm2);

    int doRes = ((long long)out_size >= 2LL * NTOT) ? 1 : 0;

    kb_f3<<<(4 * KF * NBF + 255) / 256, 256>>>();
    kb_i3<<<(4 * KI * 192 + 255) / 256, 256>>>();
    {
        size_t n = (size_t)MM * HH * LL;
        kT_pct<<<(unsigned)((n + 255) / 256), 256>>>(pct);
        kT_ipct<<<(unsigned)((n + 255) / 256), 256>>>(ipct);
    }
    // Fold + fused residual (memcpy node eliminated)
    k_fold4<<<(NRr * 181 + 255) / 256, 256>>>(x, p_fold, out + NTOT, doRes);

    g1f96<<<dim3(NRr / 128, 4), 256>>>(p_fold, p_Bf, p_xm);

    k2_pct<<<dim3(12, 3, MM), 256>>>(weight);
    k3_ipct<<<dim3(12, 6, MM), 256>>>();

    g4c<<<dim3(NRr / 64, 3), 256>>>(p_xm2, p_Bi, out);
}